// round 10
// baseline (speedup 1.0000x reference)
#include <cuda_runtime.h>

#define BB 64
#define EE 8978
#define E2C 4489
#define N1 (BB*EE)            // 574592
#define N2 (BB*E2C)           // 287296
#define SLOPE 0.33f
#define EPSBN 1e-5f

// ---------------- device scratch ----------------
__device__ float g_out32[9193472];   // pooled pre-BN (N2*32); later layer1 pre-BN out
__device__ float g_xp  [9193472];    // act0 output = layer1 T0
__device__ float g_Ta  [9193472];    // layer1 T1
__device__ float g_Tb  [9193472];    // layer1 T2
__device__ float g_Tcc [9193472];    // layer1 T3
__device__ float g_Y [N2*4];         // layer2 projected field
__device__ float g_U1[N2*4];
__device__ float g_U2[N2*4];
__device__ float g_z[N2];
__device__ float g_H1[64*256];
__device__ float g_H2[64*128];
__device__ double g_acc0[64];
__device__ double g_acc1[64];
__device__ double g_acc2[2];
__device__ float g_scale0[32], g_shift0[32];
__device__ float g_scale1[32], g_shift1[32];
__device__ float g_scale2[1],  g_shift2[1];

// ---------------- init ----------------
__global__ void kZero() {
    int t = threadIdx.x;
    if (t < 64) g_acc0[t] = 0.0;
    else if (t < 128) g_acc1[t - 64] = 0.0;
    else if (t < 130) g_acc2[t - 128] = 0.0;
}

// ---------------- fused layer0: block per graph, fields in smem ----------------
__global__ void kL0(const float* __restrict__ x, const int* __restrict__ src,
                    const float* __restrict__ ew, const float* __restrict__ W0,
                    const float* __restrict__ b0) {
    extern __shared__ float sm[];
    float* xs  = sm;
    float* t1s = sm + EE;
    float* t2s = sm + 2 * EE;
    __shared__ float s_sum[32], s_sq[32];

    int g = blockIdx.x;
    int tid = threadIdx.x;
    int lane = tid & 31, warp = tid >> 5;      // 32 warps of 1024 threads
    int nbase = g * EE;
    int ebase = nbase * 16;

    for (int i = tid; i < EE; i += 1024) xs[i] = x[nbase + i];
    if (tid < 32) { s_sum[tid] = 0.f; s_sq[tid] = 0.f; }
    __syncthreads();

    // step1: T1 = x - L x
    for (int p = warp; p < E2C; p += 32) {
        int e = ebase + p * 32 + lane;
        int ls = src[e] - nbase;
        float a = ew[e] * xs[ls];
        a += __shfl_xor_sync(~0u, a, 8);
        a += __shfl_xor_sync(~0u, a, 4);
        a += __shfl_xor_sync(~0u, a, 2);
        a += __shfl_xor_sync(~0u, a, 1);
        if (lane == 0)  t1s[2 * p]     = xs[2 * p]     - a;
        if (lane == 16) t1s[2 * p + 1] = xs[2 * p + 1] - a;
    }
    __syncthreads();

    // step2: T2 = (3 T1 - L T1 - x) / 2
    for (int p = warp; p < E2C; p += 32) {
        int e = ebase + p * 32 + lane;
        int ls = src[e] - nbase;
        float a = ew[e] * t1s[ls];
        a += __shfl_xor_sync(~0u, a, 8);
        a += __shfl_xor_sync(~0u, a, 4);
        a += __shfl_xor_sync(~0u, a, 2);
        a += __shfl_xor_sync(~0u, a, 1);
        if (lane == 0)  t2s[2 * p]     = 0.5f * (3.f * t1s[2 * p]     - a - xs[2 * p]);
        if (lane == 16) t2s[2 * p + 1] = 0.5f * (3.f * t1s[2 * p + 1] - a - xs[2 * p + 1]);
    }
    __syncthreads();

    // step3: T3 = (5 T2 - L T2 - 2 T1)/3 ; project to 32 ch; pre-BN max pool
    float w0 = W0[lane], w1 = W0[32 + lane], w2 = W0[64 + lane], w3 = W0[96 + lane];
    float bb = b0[lane];
    float lsum = 0.f, lsq = 0.f;
    for (int p = warp; p < E2C; p += 32) {
        int e = ebase + p * 32 + lane;
        int ls = src[e] - nbase;
        float a = ew[e] * t2s[ls];
        a += __shfl_xor_sync(~0u, a, 8);
        a += __shfl_xor_sync(~0u, a, 4);
        a += __shfl_xor_sync(~0u, a, 2);
        a += __shfl_xor_sync(~0u, a, 1);
        float t3 = 0.f;
        if ((lane & 15) == 0) {
            int n = 2 * p + (lane >> 4);
            t3 = (5.f * t2s[n] - a - 2.f * t1s[n]) * (1.f / 3.f);
        }
        float t3a = __shfl_sync(~0u, t3, 0);
        float t3b = __shfl_sync(~0u, t3, 16);
        float xa  = xs[2 * p],  xb  = xs[2 * p + 1];
        float ta1 = t1s[2 * p], tb1 = t1s[2 * p + 1];
        float ta2 = t2s[2 * p], tb2 = t2s[2 * p + 1];
        float oa = fmaf(xa, w0, fmaf(ta1, w1, fmaf(ta2, w2, fmaf(t3a, w3, bb))));
        float ob = fmaf(xb, w0, fmaf(tb1, w1, fmaf(tb2, w2, fmaf(t3b, w3, bb))));
        lsum += oa + ob;
        lsq  += oa * oa + ob * ob;
        g_out32[((size_t)(g * E2C + p)) * 32 + lane] = fmaxf(oa, ob);
    }
    atomicAdd(&s_sum[lane], lsum);
    atomicAdd(&s_sq[lane], lsq);
    __syncthreads();
    if (tid < 32) {
        atomicAdd(&g_acc0[tid],      (double)s_sum[tid]);
        atomicAdd(&g_acc0[32 + tid], (double)s_sq[tid]);
    }
}

// ---------------- BN finalize ----------------
__global__ void kBNfin(const double* __restrict__ acc, const double* __restrict__ accsq,
                       const float* __restrict__ g, const float* __restrict__ be,
                       float* scale, float* shift, int nCh, double invN) {
    int c = threadIdx.x;
    if (c >= nCh) return;
    double mean = acc[c] * invN;
    double var  = accsq[c] * invN - mean * mean;
    float scl = g[c] * rsqrtf((float)var + EPSBN);
    scale[c] = scl;
    shift[c] = be[c] - (float)mean * scl;
}

// ---------------- fused layer1 recurrence: block = (graph, 4-channel group) ----
// smem fields T0,T1,T2 (E2C x 4 floats each = 215.5KB total). BN0+leaky folded
// into the load of T0. All gathers are LDS; edges stream from L2.
// Writes g_xp (act0), g_Ta (T1), g_Tb (T2), g_Tcc (T3) for the GEMM.
__global__ void kL1(const int* __restrict__ src, const float* __restrict__ ew) {
    extern __shared__ float sm[];
    float* T0s = sm;                  // later reused for T3
    float* T1s = sm + E2C * 4;
    float* T2s = sm + E2C * 8;

    int bx = blockIdx.x;
    int g  = bx >> 3;
    int cg = bx & 7;                  // channel group: channels cg*4 .. cg*4+3
    int nbase = g * E2C;
    int ebase = nbase * 16;
    int tid = threadIdx.x;
    int lane = tid & 31, warp = tid >> 5;   // 32 warps
    int c = lane & 3, jslot = lane >> 2;    // 8 edge slots x 4 channels

    // load phase: BN0 + leaky -> T0 slice; also emit g_xp
    float4 scv = *(const float4*)&g_scale0[cg * 4];
    float4 shv = *(const float4*)&g_shift0[cg * 4];
    for (int n = tid; n < E2C; n += 1024) {
        float4 v = *(const float4*)&g_out32[((size_t)(nbase + n)) * 32 + cg * 4];
        v.x = fmaf(v.x, scv.x, shv.x); v.x = v.x > 0.f ? v.x : SLOPE * v.x;
        v.y = fmaf(v.y, scv.y, shv.y); v.y = v.y > 0.f ? v.y : SLOPE * v.y;
        v.z = fmaf(v.z, scv.z, shv.z); v.z = v.z > 0.f ? v.z : SLOPE * v.z;
        v.w = fmaf(v.w, scv.w, shv.w); v.w = v.w > 0.f ? v.w : SLOPE * v.w;
        *(float4*)&T0s[n * 4] = v;
        *(float4*)&g_xp[((size_t)(nbase + n)) * 32 + cg * 4] = v;
    }
    __syncthreads();

    // step1: T1 = T0 - L T0
    for (int n = warp; n < E2C; n += 32) {
        int e0 = ebase + n * 16;
        int   sa = src[e0 + jslot] - nbase;
        float wa = ew [e0 + jslot];
        int   sb = src[e0 + 8 + jslot] - nbase;
        float wb = ew [e0 + 8 + jslot];
        float acc = wa * T0s[sa * 4 + c] + wb * T0s[sb * 4 + c];
        acc += __shfl_xor_sync(~0u, acc, 4);
        acc += __shfl_xor_sync(~0u, acc, 8);
        acc += __shfl_xor_sync(~0u, acc, 16);
        if (jslot == 0) T1s[n * 4 + c] = T0s[n * 4 + c] - acc;
    }
    __syncthreads();

    // step2: T2 = 1.5 T1 - 0.5 L T1 - 0.5 T0
    for (int n = warp; n < E2C; n += 32) {
        int e0 = ebase + n * 16;
        int   sa = src[e0 + jslot] - nbase;
        float wa = ew [e0 + jslot];
        int   sb = src[e0 + 8 + jslot] - nbase;
        float wb = ew [e0 + 8 + jslot];
        float acc = wa * T1s[sa * 4 + c] + wb * T1s[sb * 4 + c];
        acc += __shfl_xor_sync(~0u, acc, 4);
        acc += __shfl_xor_sync(~0u, acc, 8);
        acc += __shfl_xor_sync(~0u, acc, 16);
        if (jslot == 0)
            T2s[n * 4 + c] = 1.5f * T1s[n * 4 + c] - 0.5f * acc - 0.5f * T0s[n * 4 + c];
    }
    __syncthreads();

    // step3: T3 = (5 T2 - L T2 - 2 T1)/3  -> overwrites T0s (dead)
    for (int n = warp; n < E2C; n += 32) {
        int e0 = ebase + n * 16;
        int   sa = src[e0 + jslot] - nbase;
        float wa = ew [e0 + jslot];
        int   sb = src[e0 + 8 + jslot] - nbase;
        float wb = ew [e0 + 8 + jslot];
        float acc = wa * T2s[sa * 4 + c] + wb * T2s[sb * 4 + c];
        acc += __shfl_xor_sync(~0u, acc, 4);
        acc += __shfl_xor_sync(~0u, acc, 8);
        acc += __shfl_xor_sync(~0u, acc, 16);
        if (jslot == 0)
            T0s[n * 4 + c] = (5.f * T2s[n * 4 + c] - acc - 2.f * T1s[n * 4 + c]) * (1.f / 3.f);
    }
    __syncthreads();

    // store phase: T1, T2, T3 slices
    for (int n = tid; n < E2C; n += 1024) {
        size_t o = ((size_t)(nbase + n)) * 32 + cg * 4;
        *(float4*)&g_Ta [o] = *(const float4*)&T1s[n * 4];
        *(float4*)&g_Tb [o] = *(const float4*)&T2s[n * 4];
        *(float4*)&g_Tcc[o] = *(const float4*)&T0s[n * 4];
    }
}

// ---------------- layer1 output GEMM + BN1 stats ----------------
__global__ void kGemmOut1(const float* __restrict__ W1, const float* __restrict__ b1) {
    __shared__ float Wsh[128 * 32];
    __shared__ float Tsh[64 * 32];
    __shared__ float ssum[32], ssq[32];
    int tid = threadIdx.x, c = tid & 31, rg = tid >> 5;
    for (int i = tid; i < 4096; i += 256) Wsh[i] = W1[i];
    if (tid < 32) { ssum[tid] = 0.f; ssq[tid] = 0.f; }
    int n0 = blockIdx.x * 64;
    float acc[8];
#pragma unroll
    for (int q = 0; q < 8; q++) acc[q] = 0.f;
    const float* Tarr[4] = { g_xp, g_Ta, g_Tb, g_Tcc };
    for (int k = 0; k < 4; k++) {
        __syncthreads();
        const float* T = Tarr[k];
#pragma unroll
        for (int q = 0; q < 8; q++)
            Tsh[(rg + 8 * q) * 32 + c] = T[(n0 + rg + 8 * q) * 32 + c];
        __syncthreads();
#pragma unroll
        for (int i = 0; i < 32; i += 4) {
            float wa = Wsh[(k * 32 + i) * 32 + c];
            float wb = Wsh[(k * 32 + i + 1) * 32 + c];
            float wc = Wsh[(k * 32 + i + 2) * 32 + c];
            float wd = Wsh[(k * 32 + i + 3) * 32 + c];
#pragma unroll
            for (int q = 0; q < 8; q++) {
                float4 t = *(const float4*)&Tsh[(rg + 8 * q) * 32 + i];
                acc[q] += t.x * wa + t.y * wb + t.z * wc + t.w * wd;
            }
        }
    }
    float bv = b1[c];
    float lsum = 0.f, lsq = 0.f;
#pragma unroll
    for (int q = 0; q < 8; q++) {
        float o = acc[q] + bv;
        g_out32[(n0 + rg + 8 * q) * 32 + c] = o;
        lsum += o; lsq += o * o;
    }
    atomicAdd(&ssum[c], lsum);
    atomicAdd(&ssq[c], lsq);
    __syncthreads();
    if (tid < 32) {
        atomicAdd(&g_acc1[tid], (double)ssum[tid]);
        atomicAdd(&g_acc1[32 + tid], (double)ssq[tid]);
    }
}

// ---------------- layer2 input: BN1 + LeakyReLU + project to 4 channels -------
__global__ void kAct1Y(const float* __restrict__ W2) {
    int warp = (blockIdx.x * blockDim.x + threadIdx.x) >> 5;   // = node
    int lane = threadIdx.x & 31;
    float o = g_out32[warp * 32 + lane];
    float v = o * g_scale1[lane] + g_shift1[lane];
    v = v > 0.f ? v : SLOPE * v;
    float y0, y1, y2, y3;
    {
        float p = v * W2[lane];
#pragma unroll
        for (int off = 16; off; off >>= 1) p += __shfl_xor_sync(~0u, p, off);
        y0 = p;
    }
    {
        float p = v * W2[32 + lane];
#pragma unroll
        for (int off = 16; off; off >>= 1) p += __shfl_xor_sync(~0u, p, off);
        y1 = p;
    }
    {
        float p = v * W2[64 + lane];
#pragma unroll
        for (int off = 16; off; off >>= 1) p += __shfl_xor_sync(~0u, p, off);
        y2 = p;
    }
    {
        float p = v * W2[96 + lane];
#pragma unroll
        for (int off = 16; off; off >>= 1) p += __shfl_xor_sync(~0u, p, off);
        y3 = p;
    }
    if (lane < 4) {
        float val = (lane == 0) ? y0 : (lane == 1) ? y1 : (lane == 2) ? y2 : y3;
        g_Y[warp * 4 + lane] = val;
    }
}

// ---------------- 4-channel matvec on Y-field (layer2 recurrence) -------------
__global__ void kMVY(const float* __restrict__ vin, const float* __restrict__ p1,
                     const int* __restrict__ src, const float* __restrict__ ew,
                     float* __restrict__ out, float ca, float cb, float cc) {
    __shared__ int   s_src[16 * 65];
    __shared__ float s_ew [16 * 65];
    int tid = threadIdx.x;
    int e0 = blockIdx.x * 1024;
#pragma unroll
    for (int t = tid; t < 1024; t += 256) {
        int j = t & 15, local = t >> 4;
        s_src[j * 65 + local] = src[e0 + t];
        s_ew [j * 65 + local] = ew [e0 + t];
    }
    __syncthreads();
    int lane = tid & 31;
    int local = (tid >> 5) * 8 + (lane >> 2);   // node within block
    int ch = lane & 3;
    int node = blockIdx.x * 64 + local;
    float acc = 0.f;
#pragma unroll
    for (int j = 0; j < 16; j++) {
        int s   = s_src[j * 65 + local];
        float w = s_ew [j * 65 + local];
        acc += w * vin[s * 4 + ch];
    }
    float o = ca * vin[node * 4 + ch] + cc * acc;
    if (cb != 0.f) o += cb * p1[node * 4 + ch];
    out[node * 4 + ch] = o;
}

// final layer2 step: u3 = (5 U2 - L U2 - 2 U1)/3 ; z = Y0 + U1_1 + U2_2 + u3_3 + b2
__global__ void kMVY3C(const int* __restrict__ src, const float* __restrict__ ew,
                       const float* __restrict__ b2) {
    __shared__ int   s_src[16 * 65];
    __shared__ float s_ew [16 * 65];
    __shared__ float bs[2];
    int tid = threadIdx.x;
    int e0 = blockIdx.x * 1024;
    if (tid < 2) bs[tid] = 0.f;
#pragma unroll
    for (int t = tid; t < 1024; t += 256) {
        int j = t & 15, local = t >> 4;
        s_src[j * 65 + local] = src[e0 + t];
        s_ew [j * 65 + local] = ew [e0 + t];
    }
    __syncthreads();
    int lane = tid & 31;
    int local = (tid >> 5) * 8 + (lane >> 2);
    int ch = lane & 3;
    int node = blockIdx.x * 64 + local;
    float acc = 0.f;
#pragma unroll
    for (int j = 0; j < 16; j++) {
        int s   = s_src[j * 65 + local];
        float w = s_ew [j * 65 + local];
        acc += w * g_U2[s * 4 + ch];
    }
    float u2v = g_U2[node * 4 + ch];
    float u1v = g_U1[node * 4 + ch];
    float yv  = g_Y [node * 4 + ch];
    float u3  = (5.f * u2v - acc - 2.f * u1v) * (1.f / 3.f);
    int base = lane & ~3;
    float zY  = __shfl_sync(~0u, yv,  base + 0);
    float zU1 = __shfl_sync(~0u, u1v, base + 1);
    float zU2 = __shfl_sync(~0u, u2v, base + 2);
    float zU3 = __shfl_sync(~0u, u3,  base + 3);
    if (ch == 0) {
        float z = zY + zU1 + zU2 + zU3 + b2[0];
        g_z[node] = z;
        atomicAdd(&bs[0], z);
        atomicAdd(&bs[1], z * z);
    }
    __syncthreads();
    if (tid == 0) {
        atomicAdd(&g_acc2[0], (double)bs[0]);
        atomicAdd(&g_acc2[1], (double)bs[1]);
    }
}

// ---------------- MLP head ----------------
__global__ void kD1(const float* __restrict__ lin1W, const float* __restrict__ lin1b) {
    __shared__ float As[16][64];
    __shared__ float Ws[64][8];
    int tid = threadIdx.x;
    int c = tid & 7, r = tid >> 3;
    int c0 = (blockIdx.x & 31) * 8;
    int r0 = (blockIdx.x >> 5) * 16;
    float scale = g_scale2[0], shift = g_shift2[0];
    float acc = 0.f;
    for (int e0 = 0; e0 < E2C; e0 += 64) {
        __syncthreads();
        for (int t = tid; t < 1024; t += 128) {
            int rr = t >> 6, ii = t & 63, e = e0 + ii;
            float v = 0.f;
            if (e < E2C) {
                float z = g_z[(r0 + rr) * E2C + e] * scale + shift;
                v = z > 0.f ? z : SLOPE * z;
            }
            As[rr][ii] = v;
        }
        for (int t = tid; t < 512; t += 128) {
            int ii = t >> 3, cc = t & 7, e = e0 + ii;
            Ws[ii][cc] = (e < E2C) ? lin1W[e * 256 + c0 + cc] : 0.f;
        }
        __syncthreads();
#pragma unroll 8
        for (int i = 0; i < 64; i++) acc += As[r][i] * Ws[i][c];
    }
    g_H1[(r0 + r) * 256 + c0 + c] = acc + lin1b[c0 + c];
}

__global__ void kD2(const float* __restrict__ bn1g, const float* __restrict__ bn1b,
                    const float* __restrict__ lin2W, const float* __restrict__ lin2b) {
    __shared__ float sc[256], sh[256], As[2][256];
    int tid = threadIdx.x;
    {
        int col = tid;
        float s = 0.f, q = 0.f;
        for (int r = 0; r < 64; r++) { float v = g_H1[r * 256 + col]; s += v; q += v * v; }
        float mean = s * (1.f / 64.f);
        float var  = q * (1.f / 64.f) - mean * mean;
        float scl = bn1g[col] * rsqrtf(var + EPSBN);
        sc[col] = scl; sh[col] = bn1b[col] - mean * scl;
    }
    __syncthreads();
    int r0 = blockIdx.x * 2;
    for (int t = tid; t < 512; t += 256) {
        int rr = t >> 8, k = t & 255;
        float v = g_H1[(r0 + rr) * 256 + k] * sc[k] + sh[k];
        As[rr][k] = v > 0.f ? v : 0.f;
    }
    __syncthreads();
    int c = tid & 127, rr = tid >> 7;
    float acc = lin2b[c];
#pragma unroll 8
    for (int k = 0; k < 256; k++) acc += As[rr][k] * lin2W[k * 128 + c];
    g_H2[(r0 + rr) * 128 + c] = acc;
}

__global__ void kD3(const float* __restrict__ bn2g, const float* __restrict__ bn2b,
                    const float* __restrict__ lin3W, const float* __restrict__ lin3b,
                    float* __restrict__ out) {
    __shared__ float sc[128], sh[128];
    int tid = threadIdx.x;
    if (tid < 128) {
        float s = 0.f, q = 0.f;
        for (int r = 0; r < 64; r++) { float v = g_H2[r * 128 + tid]; s += v; q += v * v; }
        float mean = s * (1.f / 64.f);
        float var  = q * (1.f / 64.f) - mean * mean;
        float scl = bn2g[tid] * rsqrtf(var + EPSBN);
        sc[tid] = scl; sh[tid] = bn2b[tid] - mean * scl;
    }
    __syncthreads();
    int lane = tid & 31, w = tid >> 5;
    for (int r = w; r < 64; r += 8) {
        float acc = 0.f;
        for (int kk = lane; kk < 128; kk += 32) {
            float v = g_H2[r * 128 + kk] * sc[kk] + sh[kk];
            v = v > 0.f ? v : 0.f;
            acc += v * lin3W[kk];
        }
#pragma unroll
        for (int off = 16; off; off >>= 1)
            acc += __shfl_xor_sync(0xffffffffu, acc, off);
        if (lane == 0) out[r] = acc + lin3b[0];
    }
}

// ---------------- host launcher ----------------
extern "C" void kernel_launch(void* const* d_in, const int* in_sizes, int n_in,
                              void* d_out, int out_size) {
    const float* x    = (const float*)d_in[0];
    const int*   src1 = (const int*)  d_in[1];
    const float* ew1  = (const float*)d_in[2];
    const int*   src2 = (const int*)  d_in[3];
    const float* ew2  = (const float*)d_in[4];
    const float* W0 = (const float*)d_in[5];
    const float* b0 = (const float*)d_in[6];
    const float* g0 = (const float*)d_in[7];
    const float* be0= (const float*)d_in[8];
    const float* W1 = (const float*)d_in[9];
    const float* b1 = (const float*)d_in[10];
    const float* g1 = (const float*)d_in[11];
    const float* be1= (const float*)d_in[12];
    const float* W2 = (const float*)d_in[13];
    const float* b2 = (const float*)d_in[14];
    const float* g2 = (const float*)d_in[15];
    const float* be2= (const float*)d_in[16];
    const float* lin1W = (const float*)d_in[17];
    const float* lin1b = (const float*)d_in[18];
    const float* bn1g  = (const float*)d_in[19];
    const float* bn1b  = (const float*)d_in[20];
    const float* lin2W = (const float*)d_in[21];
    const float* lin2b = (const float*)d_in[22];
    const float* bn2g  = (const float*)d_in[23];
    const float* bn2b  = (const float*)d_in[24];
    const float* lin3W = (const float*)d_in[25];
    const float* lin3b = (const float*)d_in[26];
    float* out = (float*)d_out;

    double *acc0, *acc1, *acc2;
    float *sc0, *sf0, *sc1, *sf1, *sc2, *sf2;
    cudaGetSymbolAddress((void**)&acc0, g_acc0);
    cudaGetSymbolAddress((void**)&acc1, g_acc1);
    cudaGetSymbolAddress((void**)&acc2, g_acc2);
    cudaGetSymbolAddress((void**)&sc0, g_scale0);
    cudaGetSymbolAddress((void**)&sf0, g_shift0);
    cudaGetSymbolAddress((void**)&sc1, g_scale1);
    cudaGetSymbolAddress((void**)&sf1, g_shift1);
    cudaGetSymbolAddress((void**)&sc2, g_scale2);
    cudaGetSymbolAddress((void**)&sf2, g_shift2);
    float *pY, *pU1, *pU2;
    cudaGetSymbolAddress((void**)&pY,   g_Y);
    cudaGetSymbolAddress((void**)&pU1,  g_U1);
    cudaGetSymbolAddress((void**)&pU2,  g_U2);

    const int kL0smem = 3 * EE * (int)sizeof(float);        // 107,736 B
    const int kL1smem = 12 * E2C * (int)sizeof(float);      // 215,472 B
    cudaFuncSetAttribute(kL0, cudaFuncAttributeMaxDynamicSharedMemorySize, kL0smem);
    cudaFuncSetAttribute(kL1, cudaFuncAttributeMaxDynamicSharedMemorySize, kL1smem);

    kZero<<<1, 256>>>();

    // ---- layer0 fused ----
    kL0<<<BB, 1024, kL0smem>>>(x, src1, ew1, W0, b0);
    kBNfin<<<1, 32>>>(acc0, acc0 + 32, g0, be0, sc0, sf0, 32, 1.0 / (double)N1);

    // ---- layer1: fused recurrence (act0 + 3 matvecs in smem) + GEMM ----
    kL1<<<BB * 8, 1024, kL1smem>>>(src2, ew2);
    kGemmOut1<<<N2 / 64, 256>>>(W1, b1);
    kBNfin<<<1, 32>>>(acc1, acc1 + 32, g1, be1, sc1, sf1, 32, 1.0 / (double)N2);

    // ---- layer2 collapsed to 4-channel recurrence (round-6 split kernels) ----
    kAct1Y<<<N2 / 8, 256>>>(W2);
    kMVY<<<N2 / 64, 256>>>(pY,  pY, src2, ew2, pU1, 1.0f, 0.0f, -1.0f);
    kMVY<<<N2 / 64, 256>>>(pU1, pY, src2, ew2, pU2, 1.5f, -0.5f, -0.5f);
    kMVY3C<<<N2 / 64, 256>>>(src2, ew2, b2);
    kBNfin<<<1, 32>>>(acc2, acc2 + 1, g2, be2, sc2, sf2, 1, 1.0 / (double)N2);

    // ---- MLP head ----
    kD1<<<128, 128>>>(lin1W, lin1b);
    kD2<<<32, 256>>>(bn1g, bn1b, lin2W, lin2b);
    kD3<<<1, 256>>>(bn2g, bn2b, lin3W, lin3b, out);
}

// round 14
// speedup vs baseline: 1.5808x; 1.5808x over previous
#include <cuda_runtime.h>

#define BB 64
#define EE 8978
#define E2C 4489
#define N1 (BB*EE)            // 574592
#define N2 (BB*E2C)           // 287296
#define SLOPE 0.33f
#define EPSBN 1e-5f

// ---------------- device scratch ----------------
__device__ float g_out32[9193472];   // pooled pre-BN (N2*32); later layer1 pre-BN out
__device__ float g_xp  [9193472];    // act0 output = layer1 T0
__device__ float g_Ta  [9193472];    // layer1 T1
__device__ float g_Tb  [9193472];    // layer1 T2
__device__ float g_Tcc [9193472];    // layer1 T3
__device__ float g_Y [N2*4];         // layer2 projected field
__device__ float g_U1[N2*4];
__device__ float g_U2[N2*4];
__device__ float g_z[N2];
__device__ float g_H1[64*256];
__device__ float g_H2[64*128];
__device__ double g_acc0[64];
__device__ double g_acc1[64];
__device__ double g_acc2[2];
__device__ float g_scale0[32], g_shift0[32];
__device__ float g_scale1[32], g_shift1[32];
__device__ float g_scale2[1],  g_shift2[1];

// ---------------- init ----------------
__global__ void kZero() {
    int t = threadIdx.x;
    if (t < 64) g_acc0[t] = 0.0;
    else if (t < 128) g_acc1[t - 64] = 0.0;
    else if (t < 130) g_acc2[t - 128] = 0.0;
}

// ---------------- fused layer0: block per graph, fields in smem ----------------
__global__ void kL0(const float* __restrict__ x, const int* __restrict__ src,
                    const float* __restrict__ ew, const float* __restrict__ W0,
                    const float* __restrict__ b0) {
    extern __shared__ float sm[];
    float* xs  = sm;
    float* t1s = sm + EE;
    float* t2s = sm + 2 * EE;
    __shared__ float s_sum[32], s_sq[32];

    int g = blockIdx.x;
    int tid = threadIdx.x;
    int lane = tid & 31, warp = tid >> 5;      // 32 warps of 1024 threads
    int nbase = g * EE;
    int ebase = nbase * 16;

    for (int i = tid; i < EE; i += 1024) xs[i] = x[nbase + i];
    if (tid < 32) { s_sum[tid] = 0.f; s_sq[tid] = 0.f; }
    __syncthreads();

    // step1: T1 = x - L x
    for (int p = warp; p < E2C; p += 32) {
        int e = ebase + p * 32 + lane;
        int ls = src[e] - nbase;
        float a = ew[e] * xs[ls];
        a += __shfl_xor_sync(~0u, a, 8);
        a += __shfl_xor_sync(~0u, a, 4);
        a += __shfl_xor_sync(~0u, a, 2);
        a += __shfl_xor_sync(~0u, a, 1);
        if (lane == 0)  t1s[2 * p]     = xs[2 * p]     - a;
        if (lane == 16) t1s[2 * p + 1] = xs[2 * p + 1] - a;
    }
    __syncthreads();

    // step2: T2 = (3 T1 - L T1 - x) / 2
    for (int p = warp; p < E2C; p += 32) {
        int e = ebase + p * 32 + lane;
        int ls = src[e] - nbase;
        float a = ew[e] * t1s[ls];
        a += __shfl_xor_sync(~0u, a, 8);
        a += __shfl_xor_sync(~0u, a, 4);
        a += __shfl_xor_sync(~0u, a, 2);
        a += __shfl_xor_sync(~0u, a, 1);
        if (lane == 0)  t2s[2 * p]     = 0.5f * (3.f * t1s[2 * p]     - a - xs[2 * p]);
        if (lane == 16) t2s[2 * p + 1] = 0.5f * (3.f * t1s[2 * p + 1] - a - xs[2 * p + 1]);
    }
    __syncthreads();

    // step3: T3 = (5 T2 - L T2 - 2 T1)/3 ; project to 32 ch; pre-BN max pool
    float w0 = W0[lane], w1 = W0[32 + lane], w2 = W0[64 + lane], w3 = W0[96 + lane];
    float bb = b0[lane];
    float lsum = 0.f, lsq = 0.f;
    for (int p = warp; p < E2C; p += 32) {
        int e = ebase + p * 32 + lane;
        int ls = src[e] - nbase;
        float a = ew[e] * t2s[ls];
        a += __shfl_xor_sync(~0u, a, 8);
        a += __shfl_xor_sync(~0u, a, 4);
        a += __shfl_xor_sync(~0u, a, 2);
        a += __shfl_xor_sync(~0u, a, 1);
        float t3 = 0.f;
        if ((lane & 15) == 0) {
            int n = 2 * p + (lane >> 4);
            t3 = (5.f * t2s[n] - a - 2.f * t1s[n]) * (1.f / 3.f);
        }
        float t3a = __shfl_sync(~0u, t3, 0);
        float t3b = __shfl_sync(~0u, t3, 16);
        float xa  = xs[2 * p],  xb  = xs[2 * p + 1];
        float ta1 = t1s[2 * p], tb1 = t1s[2 * p + 1];
        float ta2 = t2s[2 * p], tb2 = t2s[2 * p + 1];
        float oa = fmaf(xa, w0, fmaf(ta1, w1, fmaf(ta2, w2, fmaf(t3a, w3, bb))));
        float ob = fmaf(xb, w0, fmaf(tb1, w1, fmaf(tb2, w2, fmaf(t3b, w3, bb))));
        lsum += oa + ob;
        lsq  += oa * oa + ob * ob;
        g_out32[((size_t)(g * E2C + p)) * 32 + lane] = fmaxf(oa, ob);
    }
    atomicAdd(&s_sum[lane], lsum);
    atomicAdd(&s_sq[lane], lsq);
    __syncthreads();
    if (tid < 32) {
        atomicAdd(&g_acc0[tid],      (double)s_sum[tid]);
        atomicAdd(&g_acc0[32 + tid], (double)s_sq[tid]);
    }
}

// ---------------- BN finalize ----------------
__global__ void kBNfin(const double* __restrict__ acc, const double* __restrict__ accsq,
                       const float* __restrict__ g, const float* __restrict__ be,
                       float* scale, float* shift, int nCh, double invN) {
    int c = threadIdx.x;
    if (c >= nCh) return;
    double mean = acc[c] * invN;
    double var  = accsq[c] * invN - mean * mean;
    float scl = g[c] * rsqrtf((float)var + EPSBN);
    scale[c] = scl;
    shift[c] = be[c] - (float)mean * scl;
}

// ---------------- act0: BN0 + LeakyReLU on pooled values (float4) -------------
__global__ void kAct0v() {
    int i = blockIdx.x * 256 + threadIdx.x;        // over N2*8 float4s
    int cq = i & 7;
    float4 v = *(const float4*)&g_out32[i * 4];
    float4 sc = *(const float4*)&g_scale0[cq * 4];
    float4 sh = *(const float4*)&g_shift0[cq * 4];
    v.x = fmaf(v.x, sc.x, sh.x); v.x = v.x > 0.f ? v.x : SLOPE * v.x;
    v.y = fmaf(v.y, sc.y, sh.y); v.y = v.y > 0.f ? v.y : SLOPE * v.y;
    v.z = fmaf(v.z, sc.z, sh.z); v.z = v.z > 0.f ? v.z : SLOPE * v.z;
    v.w = fmaf(v.w, sc.w, sh.w); v.w = v.w > 0.f ? v.w : SLOPE * v.w;
    *(float4*)&g_xp[i * 4] = v;
}

// ---------------- pooled-graph 32-ch matvec, float4 form ----------------------
// warp = 4 nodes; lane = (node_sub, channel-quad). Moves identical bytes to the
// scalar version but 4x fewer LDG/shfl/IMAD instructions.
__global__ void kMV4(const float* __restrict__ vin, const float* __restrict__ p1,
                     const int* __restrict__ src, const float* __restrict__ ew,
                     float* __restrict__ out, float ca, float cb, float cc) {
    int warp = (blockIdx.x * blockDim.x + threadIdx.x) >> 5;   // node group of 4
    int lane = threadIdx.x & 31;
    int ns = lane >> 3, cq = lane & 7;
    int node = warp * 4 + ns;
    int e0 = node * 16 + cq;
    int   s0 = src[e0];     float w0 = ew[e0];
    int   s1 = src[e0 + 8]; float w1 = ew[e0 + 8];
    int sl = ns * 8;
    float4 acc = make_float4(0.f, 0.f, 0.f, 0.f);
#pragma unroll
    for (int j = 0; j < 8; j++) {
        int   sj = __shfl_sync(~0u, s0, sl + j);
        float wj = __shfl_sync(~0u, w0, sl + j);
        float4 v = *(const float4*)&vin[sj * 32 + cq * 4];
        acc.x = fmaf(wj, v.x, acc.x);
        acc.y = fmaf(wj, v.y, acc.y);
        acc.z = fmaf(wj, v.z, acc.z);
        acc.w = fmaf(wj, v.w, acc.w);
    }
#pragma unroll
    for (int j = 0; j < 8; j++) {
        int   sj = __shfl_sync(~0u, s1, sl + j);
        float wj = __shfl_sync(~0u, w1, sl + j);
        float4 v = *(const float4*)&vin[sj * 32 + cq * 4];
        acc.x = fmaf(wj, v.x, acc.x);
        acc.y = fmaf(wj, v.y, acc.y);
        acc.z = fmaf(wj, v.z, acc.z);
        acc.w = fmaf(wj, v.w, acc.w);
    }
    float4 own = *(const float4*)&vin[node * 32 + cq * 4];
    float4 o;
    o.x = ca * own.x + cc * acc.x;
    o.y = ca * own.y + cc * acc.y;
    o.z = ca * own.z + cc * acc.z;
    o.w = ca * own.w + cc * acc.w;
    if (cb != 0.f) {
        float4 p = *(const float4*)&p1[node * 32 + cq * 4];
        o.x += cb * p.x; o.y += cb * p.y; o.z += cb * p.z; o.w += cb * p.w;
    }
    *(float4*)&out[node * 32 + cq * 4] = o;
}

// ---------------- layer1 output GEMM + BN1 stats ----------------
__global__ void kGemmOut1(const float* __restrict__ W1, const float* __restrict__ b1) {
    __shared__ float Wsh[128 * 32];
    __shared__ float Tsh[64 * 32];
    __shared__ float ssum[32], ssq[32];
    int tid = threadIdx.x, c = tid & 31, rg = tid >> 5;
    for (int i = tid; i < 4096; i += 256) Wsh[i] = W1[i];
    if (tid < 32) { ssum[tid] = 0.f; ssq[tid] = 0.f; }
    int n0 = blockIdx.x * 64;
    float acc[8];
#pragma unroll
    for (int q = 0; q < 8; q++) acc[q] = 0.f;
    const float* Tarr[4] = { g_xp, g_Ta, g_Tb, g_Tcc };
    for (int k = 0; k < 4; k++) {
        __syncthreads();
        const float* T = Tarr[k];
#pragma unroll
        for (int q = 0; q < 8; q++)
            Tsh[(rg + 8 * q) * 32 + c] = T[(n0 + rg + 8 * q) * 32 + c];
        __syncthreads();
#pragma unroll
        for (int i = 0; i < 32; i += 4) {
            float wa = Wsh[(k * 32 + i) * 32 + c];
            float wb = Wsh[(k * 32 + i + 1) * 32 + c];
            float wc = Wsh[(k * 32 + i + 2) * 32 + c];
            float wd = Wsh[(k * 32 + i + 3) * 32 + c];
#pragma unroll
            for (int q = 0; q < 8; q++) {
                float4 t = *(const float4*)&Tsh[(rg + 8 * q) * 32 + i];
                acc[q] += t.x * wa + t.y * wb + t.z * wc + t.w * wd;
            }
        }
    }
    float bv = b1[c];
    float lsum = 0.f, lsq = 0.f;
#pragma unroll
    for (int q = 0; q < 8; q++) {
        float o = acc[q] + bv;
        g_out32[(n0 + rg + 8 * q) * 32 + c] = o;
        lsum += o; lsq += o * o;
    }
    atomicAdd(&ssum[c], lsum);
    atomicAdd(&ssq[c], lsq);
    __syncthreads();
    if (tid < 32) {
        atomicAdd(&g_acc1[tid], (double)ssum[tid]);
        atomicAdd(&g_acc1[32 + tid], (double)ssq[tid]);
    }
}

// ---------------- layer2 input: BN1 + LeakyReLU + project to 4 channels -------
__global__ void kAct1Y(const float* __restrict__ W2) {
    int warp = (blockIdx.x * blockDim.x + threadIdx.x) >> 5;   // = node
    int lane = threadIdx.x & 31;
    float o = g_out32[warp * 32 + lane];
    float v = o * g_scale1[lane] + g_shift1[lane];
    v = v > 0.f ? v : SLOPE * v;
    float y0, y1, y2, y3;
    {
        float p = v * W2[lane];
#pragma unroll
        for (int off = 16; off; off >>= 1) p += __shfl_xor_sync(~0u, p, off);
        y0 = p;
    }
    {
        float p = v * W2[32 + lane];
#pragma unroll
        for (int off = 16; off; off >>= 1) p += __shfl_xor_sync(~0u, p, off);
        y1 = p;
    }
    {
        float p = v * W2[64 + lane];
#pragma unroll
        for (int off = 16; off; off >>= 1) p += __shfl_xor_sync(~0u, p, off);
        y2 = p;
    }
    {
        float p = v * W2[96 + lane];
#pragma unroll
        for (int off = 16; off; off >>= 1) p += __shfl_xor_sync(~0u, p, off);
        y3 = p;
    }
    if (lane < 4) {
        float val = (lane == 0) ? y0 : (lane == 1) ? y1 : (lane == 2) ? y2 : y3;
        g_Y[warp * 4 + lane] = val;
    }
}

// ---------------- 4-channel matvec on Y-field (layer2 recurrence) -------------
__global__ void kMVY(const float* __restrict__ vin, const float* __restrict__ p1,
                     const int* __restrict__ src, const float* __restrict__ ew,
                     float* __restrict__ out, float ca, float cb, float cc) {
    __shared__ int   s_src[16 * 65];
    __shared__ float s_ew [16 * 65];
    int tid = threadIdx.x;
    int e0 = blockIdx.x * 1024;
#pragma unroll
    for (int t = tid; t < 1024; t += 256) {
        int j = t & 15, local = t >> 4;
        s_src[j * 65 + local] = src[e0 + t];
        s_ew [j * 65 + local] = ew [e0 + t];
    }
    __syncthreads();
    int lane = tid & 31;
    int local = (tid >> 5) * 8 + (lane >> 2);   // node within block
    int ch = lane & 3;
    int node = blockIdx.x * 64 + local;
    float acc = 0.f;
#pragma unroll
    for (int j = 0; j < 16; j++) {
        int s   = s_src[j * 65 + local];
        float w = s_ew [j * 65 + local];
        acc += w * vin[s * 4 + ch];
    }
    float o = ca * vin[node * 4 + ch] + cc * acc;
    if (cb != 0.f) o += cb * p1[node * 4 + ch];
    out[node * 4 + ch] = o;
}

// final layer2 step: u3 = (5 U2 - L U2 - 2 U1)/3 ; z = Y0 + U1_1 + U2_2 + u3_3 + b2
__global__ void kMVY3C(const int* __restrict__ src, const float* __restrict__ ew,
                       const float* __restrict__ b2) {
    __shared__ int   s_src[16 * 65];
    __shared__ float s_ew [16 * 65];
    __shared__ float bs[2];
    int tid = threadIdx.x;
    int e0 = blockIdx.x * 1024;
    if (tid < 2) bs[tid] = 0.f;
#pragma unroll
    for (int t = tid; t < 1024; t += 256) {
        int j = t & 15, local = t >> 4;
        s_src[j * 65 + local] = src[e0 + t];
        s_ew [j * 65 + local] = ew [e0 + t];
    }
    __syncthreads();
    int lane = tid & 31;
    int local = (tid >> 5) * 8 + (lane >> 2);
    int ch = lane & 3;
    int node = blockIdx.x * 64 + local;
    float acc = 0.f;
#pragma unroll
    for (int j = 0; j < 16; j++) {
        int s   = s_src[j * 65 + local];
        float w = s_ew [j * 65 + local];
        acc += w * g_U2[s * 4 + ch];
    }
    float u2v = g_U2[node * 4 + ch];
    float u1v = g_U1[node * 4 + ch];
    float yv  = g_Y [node * 4 + ch];
    float u3  = (5.f * u2v - acc - 2.f * u1v) * (1.f / 3.f);
    int base = lane & ~3;
    float zY  = __shfl_sync(~0u, yv,  base + 0);
    float zU1 = __shfl_sync(~0u, u1v, base + 1);
    float zU2 = __shfl_sync(~0u, u2v, base + 2);
    float zU3 = __shfl_sync(~0u, u3,  base + 3);
    if (ch == 0) {
        float z = zY + zU1 + zU2 + zU3 + b2[0];
        g_z[node] = z;
        atomicAdd(&bs[0], z);
        atomicAdd(&bs[1], z * z);
    }
    __syncthreads();
    if (tid == 0) {
        atomicAdd(&g_acc2[0], (double)bs[0]);
        atomicAdd(&g_acc2[1], (double)bs[1]);
    }
}

// ---------------- MLP head ----------------
__global__ void kD1(const float* __restrict__ lin1W, const float* __restrict__ lin1b) {
    __shared__ float As[16][64];
    __shared__ float Ws[64][8];
    int tid = threadIdx.x;
    int c = tid & 7, r = tid >> 3;
    int c0 = (blockIdx.x & 31) * 8;
    int r0 = (blockIdx.x >> 5) * 16;
    float scale = g_scale2[0], shift = g_shift2[0];
    float acc = 0.f;
    for (int e0 = 0; e0 < E2C; e0 += 64) {
        __syncthreads();
        for (int t = tid; t < 1024; t += 128) {
            int rr = t >> 6, ii = t & 63, e = e0 + ii;
            float v = 0.f;
            if (e < E2C) {
                float z = g_z[(r0 + rr) * E2C + e] * scale + shift;
                v = z > 0.f ? z : SLOPE * z;
            }
            As[rr][ii] = v;
        }
        for (int t = tid; t < 512; t += 128) {
            int ii = t >> 3, cc = t & 7, e = e0 + ii;
            Ws[ii][cc] = (e < E2C) ? lin1W[e * 256 + c0 + cc] : 0.f;
        }
        __syncthreads();
#pragma unroll 8
        for (int i = 0; i < 64; i++) acc += As[r][i] * Ws[i][c];
    }
    g_H1[(r0 + r) * 256 + c0 + c] = acc + lin1b[c0 + c];
}

__global__ void kD2(const float* __restrict__ bn1g, const float* __restrict__ bn1b,
                    const float* __restrict__ lin2W, const float* __restrict__ lin2b) {
    __shared__ float sc[256], sh[256], As[2][256];
    int tid = threadIdx.x;
    {
        int col = tid;
        float s = 0.f, q = 0.f;
        for (int r = 0; r < 64; r++) { float v = g_H1[r * 256 + col]; s += v; q += v * v; }
        float mean = s * (1.f / 64.f);
        float var  = q * (1.f / 64.f) - mean * mean;
        float scl = bn1g[col] * rsqrtf(var + EPSBN);
        sc[col] = scl; sh[col] = bn1b[col] - mean * scl;
    }
    __syncthreads();
    int r0 = blockIdx.x * 2;
    for (int t = tid; t < 512; t += 256) {
        int rr = t >> 8, k = t & 255;
        float v = g_H1[(r0 + rr) * 256 + k] * sc[k] + sh[k];
        As[rr][k] = v > 0.f ? v : 0.f;
    }
    __syncthreads();
    int c = tid & 127, rr = tid >> 7;
    float acc = lin2b[c];
#pragma unroll 8
    for (int k = 0; k < 256; k++) acc += As[rr][k] * lin2W[k * 128 + c];
    g_H2[(r0 + rr) * 128 + c] = acc;
}

__global__ void kD3(const float* __restrict__ bn2g, const float* __restrict__ bn2b,
                    const float* __restrict__ lin3W, const float* __restrict__ lin3b,
                    float* __restrict__ out) {
    __shared__ float sc[128], sh[128];
    int tid = threadIdx.x;
    if (tid < 128) {
        float s = 0.f, q = 0.f;
        for (int r = 0; r < 64; r++) { float v = g_H2[r * 128 + tid]; s += v; q += v * v; }
        float mean = s * (1.f / 64.f);
        float var  = q * (1.f / 64.f) - mean * mean;
        float scl = bn2g[tid] * rsqrtf(var + EPSBN);
        sc[tid] = scl; sh[tid] = bn2b[tid] - mean * scl;
    }
    __syncthreads();
    int lane = tid & 31, w = tid >> 5;
    for (int r = w; r < 64; r += 8) {
        float acc = 0.f;
        for (int kk = lane; kk < 128; kk += 32) {
            float v = g_H2[r * 128 + kk] * sc[kk] + sh[kk];
            v = v > 0.f ? v : 0.f;
            acc += v * lin3W[kk];
        }
#pragma unroll
        for (int off = 16; off; off >>= 1)
            acc += __shfl_xor_sync(0xffffffffu, acc, off);
        if (lane == 0) out[r] = acc + lin3b[0];
    }
}

// ---------------- host launcher ----------------
extern "C" void kernel_launch(void* const* d_in, const int* in_sizes, int n_in,
                              void* d_out, int out_size) {
    const float* x    = (const float*)d_in[0];
    const int*   src1 = (const int*)  d_in[1];
    const float* ew1  = (const float*)d_in[2];
    const int*   src2 = (const int*)  d_in[3];
    const float* ew2  = (const float*)d_in[4];
    const float* W0 = (const float*)d_in[5];
    const float* b0 = (const float*)d_in[6];
    const float* g0 = (const float*)d_in[7];
    const float* be0= (const float*)d_in[8];
    const float* W1 = (const float*)d_in[9];
    const float* b1 = (const float*)d_in[10];
    const float* g1 = (const float*)d_in[11];
    const float* be1= (const float*)d_in[12];
    const float* W2 = (const float*)d_in[13];
    const float* b2 = (const float*)d_in[14];
    const float* g2 = (const float*)d_in[15];
    const float* be2= (const float*)d_in[16];
    const float* lin1W = (const float*)d_in[17];
    const float* lin1b = (const float*)d_in[18];
    const float* bn1g  = (const float*)d_in[19];
    const float* bn1b  = (const float*)d_in[20];
    const float* lin2W = (const float*)d_in[21];
    const float* lin2b = (const float*)d_in[22];
    const float* bn2g  = (const float*)d_in[23];
    const float* bn2b  = (const float*)d_in[24];
    const float* lin3W = (const float*)d_in[25];
    const float* lin3b = (const float*)d_in[26];
    float* out = (float*)d_out;

    double *acc0, *acc1, *acc2;
    float *sc0, *sf0, *sc1, *sf1, *sc2, *sf2;
    cudaGetSymbolAddress((void**)&acc0, g_acc0);
    cudaGetSymbolAddress((void**)&acc1, g_acc1);
    cudaGetSymbolAddress((void**)&acc2, g_acc2);
    cudaGetSymbolAddress((void**)&sc0, g_scale0);
    cudaGetSymbolAddress((void**)&sf0, g_shift0);
    cudaGetSymbolAddress((void**)&sc1, g_scale1);
    cudaGetSymbolAddress((void**)&sf1, g_shift1);
    cudaGetSymbolAddress((void**)&sc2, g_scale2);
    cudaGetSymbolAddress((void**)&sf2, g_shift2);
    float *pXp, *pTa, *pTb, *pTcc, *pY, *pU1, *pU2;
    cudaGetSymbolAddress((void**)&pXp,  g_xp);
    cudaGetSymbolAddress((void**)&pTa,  g_Ta);
    cudaGetSymbolAddress((void**)&pTb,  g_Tb);
    cudaGetSymbolAddress((void**)&pTcc, g_Tcc);
    cudaGetSymbolAddress((void**)&pY,   g_Y);
    cudaGetSymbolAddress((void**)&pU1,  g_U1);
    cudaGetSymbolAddress((void**)&pU2,  g_U2);

    const int kL0smem = 3 * EE * (int)sizeof(float);   // 107,736 B
    cudaFuncSetAttribute(kL0, cudaFuncAttributeMaxDynamicSharedMemorySize, kL0smem);

    kZero<<<1, 256>>>();

    // ---- layer0 fused ----
    kL0<<<BB, 1024, kL0smem>>>(x, src1, ew1, W0, b0);
    kBNfin<<<1, 32>>>(acc0, acc0 + 32, g0, be0, sc0, sf0, 32, 1.0 / (double)N1);
    kAct0v<<<(N2 * 8) / 256, 256>>>();

    // ---- layer1 (32 channels, pooled graph) — float4 gather matvecs ----
    kMV4<<<N2 / 32, 256>>>(pXp, pXp, src2, ew2, pTa, 1.0f, 0.0f, -1.0f);
    kMV4<<<N2 / 32, 256>>>(pTa, pXp, src2, ew2, pTb, 1.5f, -0.5f, -0.5f);
    kMV4<<<N2 / 32, 256>>>(pTb, pTa, src2, ew2, pTcc, 5.f/3.f, -2.f/3.f, -1.f/3.f);
    kGemmOut1<<<N2 / 64, 256>>>(W1, b1);
    kBNfin<<<1, 32>>>(acc1, acc1 + 32, g1, be1, sc1, sf1, 32, 1.0 / (double)N2);

    // ---- layer2 collapsed to 4-channel recurrence ----
    kAct1Y<<<N2 / 8, 256>>>(W2);
    kMVY<<<N2 / 64, 256>>>(pY,  pY, src2, ew2, pU1, 1.0f, 0.0f, -1.0f);
    kMVY<<<N2 / 64, 256>>>(pU1, pY, src2, ew2, pU2, 1.5f, -0.5f, -0.5f);
    kMVY3C<<<N2 / 64, 256>>>(src2, ew2, b2);
    kBNfin<<<1, 32>>>(acc2, acc2 + 1, g2, be2, sc2, sf2, 1, 1.0 / (double)N2);

    // ---- MLP head ----
    kD1<<<128, 128>>>(lin1W, lin1b);
    kD2<<<32, 256>>>(bn1g, bn1b, lin2W, lin2b);
    kD3<<<1, 256>>>(bn2g, bn2b, lin3W, lin3b, out);
}